// round 6
// baseline (speedup 1.0000x reference)
#include <cuda_runtime.h>

// EMA along T with geometric-decay chunking, round 5.
// x: [B=8, T=4096, F=1024] fp32, y_t = 0.9*y_{t-1} + 0.1*x_t, y_{-1}=0.
// Each chunk reconstructs its carry from a 96-step warmup started at 0;
// truncation 0.9^97 ~ 3.6e-5 -> measured rel_err 5e-6, 200x under the gate.
//
// R5: single-variable experiment vs R4 (50.8us, DRAM 75.4% @ ~265MB = the
// compulsory-traffic floor):
//  - Bytes are at the floor and BW plateaus at ~6.0TB/s across 14 and 28
//    warps/SM (R3 controlled experiment) with dram__cycles_active only 75%
//    -> suspect read/write bus-turnaround overhead from evict-first stores.
//  - CHANGE: st.global.cs -> default write-back stores. Dirty y lines batch
//    in L2 and flush in bursts -> fewer R/W turnarounds at HBM.
//  - Everything else identical (CHUNK=256, LOOKBACK=96, float2 lanes,
//    512 blocks, chunk-major blockIdx.x).

#define T_DIM    4096
#define F_DIM    1024
#define B_DIM    8
#define CHUNK    256
#define LOOKBACK 96
#define ALPHA    0.9f
#define OMALPHA  0.1f

#define F2 (F_DIM / 2)          // 512 float2 lanes across features
#define NCHUNK (T_DIM / CHUNK)  // 16

__global__ __launch_bounds__(128, 8)
void ema_chunk_kernel(const float* __restrict__ x, float* __restrict__ y) {
    const int chunk = blockIdx.x;                             // 0..15 (fastest -> adjacent SMs)
    const int f2 = blockIdx.y * blockDim.x + threadIdx.x;     // 0..511
    const int b = blockIdx.z;                                 // 0..7

    const int t0 = chunk * CHUNK;
    const int tw = (t0 >= LOOKBACK) ? (t0 - LOOKBACK) : 0;

    const float2* __restrict__ xp =
        reinterpret_cast<const float2*>(x) + (size_t)b * T_DIM * F2 + f2;
    float2* __restrict__ yp =
        reinterpret_cast<float2*>(y) + (size_t)b * T_DIM * F2 + f2;

    float ax = 0.f, ay = 0.f;

    // ---- warmup: reconstruct carry over [tw, t0) ----
    #pragma unroll 16
    for (int t = tw; t < t0; ++t) {
        float2 v = __ldg(&xp[(size_t)t * F2]);
        ax = fmaf(ALPHA, ax, OMALPHA * v.x);
        ay = fmaf(ALPHA, ay, OMALPHA * v.y);
    }

    // ---- main: produce outputs for [t0, t0+CHUNK) ----
    #pragma unroll 16
    for (int i = 0; i < CHUNK; ++i) {
        const int tt = t0 + i;
        float2 v = __ldg(&xp[(size_t)tt * F2]);
        ax = fmaf(ALPHA, ax, OMALPHA * v.x);
        ay = fmaf(ALPHA, ay, OMALPHA * v.y);
        float2 o; o.x = ax; o.y = ay;
        yp[(size_t)tt * F2] = o;   // default write-back (R4 used st.global.cs)
    }
}

extern "C" void kernel_launch(void* const* d_in, const int* in_sizes, int n_in,
                              void* d_out, int out_size) {
    (void)in_sizes; (void)n_in; (void)out_size;
    const float* x = (const float*)d_in[0];
    float* y = (float*)d_out;

    dim3 block(128, 1, 1);
    dim3 grid(NCHUNK, F2 / 128, B_DIM);   // (16, 4, 8) = 512 blocks
    ema_chunk_kernel<<<grid, block>>>(x, y);
}

// round 7
// speedup vs baseline: 1.0062x; 1.0062x over previous
#include <cuda_runtime.h>

// EMA along T with geometric-decay chunking, round 6.
// x: [B=8, T=4096, F=1024] fp32, y_t = 0.9*y_{t-1} + 0.1*x_t, y_{-1}=0.
// Each chunk reconstructs its carry from a 96-step warmup started at 0;
// truncation 0.9^97 -> measured rel_err 5.0e-6, 200x under the 1e-3 gate.
//
// Status after R2-R5: DRAM bytes at the 268MB compulsory floor, BW pinned at
// 6.0 TB/s across every occupancy/balance/store-policy variant -> at the
// achievable HBM wall. R6 shaves the last quantifiable overhead:
//  - 512 blocks split 4/3 across SMs (68 SMs carry 33% more work, no
//    work-stealing in a single wave). Same warps in 64-thread blocks ->
//    1024 blocks, 7/6 split (~3% imbalance), identical coalescing
//    (each warp still loads 256B contiguous per timestep).
//  - revert to st.global.cs (best-timed variant; protects x in L2).

#define T_DIM    4096
#define F_DIM    1024
#define B_DIM    8
#define CHUNK    256
#define LOOKBACK 96
#define ALPHA    0.9f
#define OMALPHA  0.1f

#define F2 (F_DIM / 2)          // 512 float2 lanes across features
#define NCHUNK (T_DIM / CHUNK)  // 16
#define BTHREADS 64

__device__ __forceinline__ void stcs2(float2* p, float2 v) {
    asm volatile("st.global.cs.v2.f32 [%0], {%1,%2};"
                 :: "l"(p), "f"(v.x), "f"(v.y) : "memory");
}

__global__ __launch_bounds__(BTHREADS, 16)
void ema_chunk_kernel(const float* __restrict__ x, float* __restrict__ y) {
    const int chunk = blockIdx.x;                              // 0..15 (fastest -> adjacent SMs)
    const int f2 = blockIdx.y * BTHREADS + threadIdx.x;        // 0..511
    const int b = blockIdx.z;                                  // 0..7

    const int t0 = chunk * CHUNK;
    const int tw = (t0 >= LOOKBACK) ? (t0 - LOOKBACK) : 0;

    const float2* __restrict__ xp =
        reinterpret_cast<const float2*>(x) + (size_t)b * T_DIM * F2 + f2;
    float2* __restrict__ yp =
        reinterpret_cast<float2*>(y) + (size_t)b * T_DIM * F2 + f2;

    float ax = 0.f, ay = 0.f;

    // ---- warmup: reconstruct carry over [tw, t0) ----
    #pragma unroll 16
    for (int t = tw; t < t0; ++t) {
        float2 v = __ldg(&xp[(size_t)t * F2]);
        ax = fmaf(ALPHA, ax, OMALPHA * v.x);
        ay = fmaf(ALPHA, ay, OMALPHA * v.y);
    }

    // ---- main: produce outputs for [t0, t0+CHUNK) ----
    #pragma unroll 16
    for (int i = 0; i < CHUNK; ++i) {
        const int tt = t0 + i;
        float2 v = __ldg(&xp[(size_t)tt * F2]);
        ax = fmaf(ALPHA, ax, OMALPHA * v.x);
        ay = fmaf(ALPHA, ay, OMALPHA * v.y);
        float2 o; o.x = ax; o.y = ay;
        stcs2(&yp[(size_t)tt * F2], o);
    }
}

extern "C" void kernel_launch(void* const* d_in, const int* in_sizes, int n_in,
                              void* d_out, int out_size) {
    (void)in_sizes; (void)n_in; (void)out_size;
    const float* x = (const float*)d_in[0];
    float* y = (float*)d_out;

    dim3 block(BTHREADS, 1, 1);
    dim3 grid(NCHUNK, F2 / BTHREADS, B_DIM);   // (16, 8, 8) = 1024 blocks
    ema_chunk_kernel<<<grid, block>>>(x, y);
}

// round 8
// speedup vs baseline: 1.0788x; 1.0721x over previous
#include <cuda_runtime.h>

// EMA along T with geometric-decay chunking, round 7 (final squeeze).
// x: [B=8, T=4096, F=1024] fp32, y_t = 0.9*y_{t-1} + 0.1*x_t, y_{-1}=0.
//
// Status: DRAM bytes at the 268MB compulsory floor; achieved BW pinned at
// 6.0 TB/s across 6 config variants -> at the mixed-R/W HBM wall
// (profiled 44.0us ~= 266MB / 6.05TB/s ideal).
//
// R7: shorten the warmup. LOOKBACK 96->64 cuts per-block iterations 9%
// (352->320) and shrinks the no-store prologue every block serializes
// through. Error model (verified at L=128 and L=96: measured rel_err ~
// bound/6-7): bound 0.9^65 = 1.06e-3 -> expected measured ~1.5e-4,
// ~6x under the 1e-3 gate.
// Everything else = best-timed config: CHUNK=256, float2 lanes, 128-thread
// blocks (512 total), chunk-major blockIdx.x, st.global.cs stores.

#define T_DIM    4096
#define F_DIM    1024
#define B_DIM    8
#define CHUNK    256
#define LOOKBACK 64
#define ALPHA    0.9f
#define OMALPHA  0.1f

#define F2 (F_DIM / 2)          // 512 float2 lanes across features
#define NCHUNK (T_DIM / CHUNK)  // 16

__device__ __forceinline__ void stcs2(float2* p, float2 v) {
    asm volatile("st.global.cs.v2.f32 [%0], {%1,%2};"
                 :: "l"(p), "f"(v.x), "f"(v.y) : "memory");
}

__global__ __launch_bounds__(128, 8)
void ema_chunk_kernel(const float* __restrict__ x, float* __restrict__ y) {
    const int chunk = blockIdx.x;                             // 0..15 (fastest -> adjacent SMs)
    const int f2 = blockIdx.y * blockDim.x + threadIdx.x;     // 0..511
    const int b = blockIdx.z;                                 // 0..7

    const int t0 = chunk * CHUNK;
    const int tw = (t0 >= LOOKBACK) ? (t0 - LOOKBACK) : 0;

    const float2* __restrict__ xp =
        reinterpret_cast<const float2*>(x) + (size_t)b * T_DIM * F2 + f2;
    float2* __restrict__ yp =
        reinterpret_cast<float2*>(y) + (size_t)b * T_DIM * F2 + f2;

    float ax = 0.f, ay = 0.f;

    // ---- warmup: reconstruct carry over [tw, t0) ----
    #pragma unroll 16
    for (int t = tw; t < t0; ++t) {
        float2 v = __ldg(&xp[(size_t)t * F2]);
        ax = fmaf(ALPHA, ax, OMALPHA * v.x);
        ay = fmaf(ALPHA, ay, OMALPHA * v.y);
    }

    // ---- main: produce outputs for [t0, t0+CHUNK) ----
    #pragma unroll 16
    for (int i = 0; i < CHUNK; ++i) {
        const int tt = t0 + i;
        float2 v = __ldg(&xp[(size_t)tt * F2]);
        ax = fmaf(ALPHA, ax, OMALPHA * v.x);
        ay = fmaf(ALPHA, ay, OMALPHA * v.y);
        float2 o; o.x = ax; o.y = ay;
        stcs2(&yp[(size_t)tt * F2], o);
    }
}

extern "C" void kernel_launch(void* const* d_in, const int* in_sizes, int n_in,
                              void* d_out, int out_size) {
    (void)in_sizes; (void)n_in; (void)out_size;
    const float* x = (const float*)d_in[0];
    float* y = (float*)d_out;

    dim3 block(128, 1, 1);
    dim3 grid(NCHUNK, F2 / 128, B_DIM);   // (16, 4, 8) = 512 blocks
    ema_chunk_kernel<<<grid, block>>>(x, y);
}